// round 13
// baseline (speedup 1.0000x reference)
#include <cuda_runtime.h>
#include <cstdint>

// ---------------------------------------------------------------------------
// C[4096,18432] = A[4096,7168] * W[18432,7168]^T with per-128x128 block scales.
//  Pass 1: pack kernels  -> dequant + cvt.rna.tf32 + SW128 swizzle, tile-major
//          (widened to 8 floats/thread; layout identical to R3/R12).
//  Pass 2: GEMM          -> BYTE-IDENTICAL to the reproduced champion (R3/R12):
//          mma.sync.m16n8k8 tf32 + cp.async 4-stage pipeline,
//          wait / BAR / compute / BAR / issue per chunk. DO NOT PERTURB:
//          every structural variant tried (R4,R5,R6,R8,R9,R10) flipped the
//          compiled loop into a ~3.4x slower scheduling mode.
// ---------------------------------------------------------------------------

#define MDIM 4096
#define NDIM 18432
#define KDIM 7168
#define BM 128
#define BN 256
#define BK 32
#define KCHUNKS (KDIM / BK)          // 224
#define MTILES (MDIM / BM)           // 32
#define NTILES (NDIM / BN)           // 72
#define STAGES 4

#define A_TILE_BYTES (BM * 128)      // 16384 (128 rows x 32 tf32)
#define W_TILE_BYTES (BN * 128)      // 32768 (256 rows x 32 tf32)
#define STAGE_BYTES  (A_TILE_BYTES + W_TILE_BYTES)        // 49152
#define SMEM_TILE0   1024
#define SMEM_TOTAL   (SMEM_TILE0 + STAGES * STAGE_BYTES)  // 197632

__device__ __align__(1024) unsigned char g_ap[(size_t)MDIM * KDIM * 4];
__device__ __align__(1024) unsigned char g_wp[(size_t)NDIM * KDIM * 4];

// ---------------------------------------------------------------------------
__device__ __forceinline__ uint32_t smem_u32(const void* p) {
    uint32_t a;
    asm("{ .reg .u64 t; cvta.to.shared.u64 t, %1; cvt.u32.u64 %0, t; }" : "=r"(a) : "l"(p));
    return a;
}
__device__ __forceinline__ float rna_tf32(float x) {
    uint32_t u;
    asm("cvt.rna.tf32.f32 %0, %1;" : "=r"(u) : "f"(x));
    return __uint_as_float(u);
}
__device__ __forceinline__ uint32_t lds32(uint32_t a) {
    uint32_t v;
    asm volatile("ld.shared.b32 %0, [%1];" : "=r"(v) : "r"(a));
    return v;
}
__device__ __forceinline__ void cp16(uint32_t dst, const void* src) {
    asm volatile("cp.async.cg.shared.global [%0], [%1], 16;"
                 :: "r"(dst), "l"(__cvta_generic_to_global(src)) : "memory");
}
__device__ __forceinline__ void mma_tf32(float* d, const uint32_t* a, const uint32_t* b) {
    asm volatile(
        "mma.sync.aligned.m16n8k8.row.col.f32.tf32.tf32.f32 "
        "{%0,%1,%2,%3}, {%4,%5,%6,%7}, {%8,%9}, {%0,%1,%2,%3};"
        : "+f"(d[0]), "+f"(d[1]), "+f"(d[2]), "+f"(d[3])
        : "r"(a[0]), "r"(a[1]), "r"(a[2]), "r"(a[3]), "r"(b[0]), "r"(b[1]));
}

// ---------------------------------------------------------------------------
// Pack kernels: tile-major, tile = rows x 32 tf32, 128B/row, SW128 swizzle
// (byte = row*128 + k*4, sw = byte ^ ((byte>>3)&0x70)) — SAME layout as
// R3/R12. Widened: each thread converts 8 consecutive k-floats (2x LDG.128
// -> 2x STG.128 at sw0 and sw0^16; k%8==0 keeps both in one 32-k chunk and
// one scale block, and the swizzle xor field (off bits 7-9) is unchanged
// by +16 since off%128 in {0,32,64,96}).
// ---------------------------------------------------------------------------
__global__ __launch_bounds__(256) void pack_a_kernel(const float* __restrict__ x) {
    size_t i = (size_t)blockIdx.x * 256 + threadIdx.x;
    if (i >= (size_t)MDIM * KDIM / 8) return;
    size_t f = i * 8;
    int m = (int)(f / KDIM);
    int k = (int)(f % KDIM);
    float4 v0 = *(const float4*)(x + f);
    float4 v1 = *(const float4*)(x + f + 4);
    uint32_t off = ((uint32_t)(m & 127) << 7) + ((uint32_t)(k & 31) << 2);
    uint32_t sw = off ^ ((off >> 3) & 0x70);
    unsigned char* tile = g_ap + ((size_t)(m >> 7) * KCHUNKS + (k >> 5)) * A_TILE_BYTES;
    *(float4*)(tile + sw) =
        make_float4(rna_tf32(v0.x), rna_tf32(v0.y), rna_tf32(v0.z), rna_tf32(v0.w));
    *(float4*)(tile + (sw ^ 16)) =
        make_float4(rna_tf32(v1.x), rna_tf32(v1.y), rna_tf32(v1.z), rna_tf32(v1.w));
}

__global__ __launch_bounds__(256) void pack_w_kernel(const float* __restrict__ w,
                                                     const float* __restrict__ scale) {
    size_t i = (size_t)blockIdx.x * 256 + threadIdx.x;
    if (i >= (size_t)NDIM * KDIM / 8) return;
    size_t f = i * 8;
    int n = (int)(f / KDIM);
    int k = (int)(f % KDIM);
    float4 v0 = *(const float4*)(w + f);
    float4 v1 = *(const float4*)(w + f + 4);
    float s = scale[(size_t)(n >> 7) * (KDIM / 128) + (k >> 7)];
    uint32_t off = ((uint32_t)(n & 255) << 7) + ((uint32_t)(k & 31) << 2);
    uint32_t sw = off ^ ((off >> 3) & 0x70);
    unsigned char* tile = g_wp + ((size_t)(n >> 8) * KCHUNKS + (k >> 5)) * W_TILE_BYTES;
    *(float4*)(tile + sw) =
        make_float4(rna_tf32(v0.x * s), rna_tf32(v0.y * s),
                    rna_tf32(v0.z * s), rna_tf32(v0.w * s));
    *(float4*)(tile + (sw ^ 16)) =
        make_float4(rna_tf32(v1.x * s), rna_tf32(v1.y * s),
                    rna_tf32(v1.z * s), rna_tf32(v1.w * s));
}

// ---------------------------------------------------------------------------
// GEMM: 8 warps (2m x 4n), warp tile 64x64, mma m16n8k8 tf32.
// BYTE-IDENTICAL to the reproduced 1,482/1,486 us champion. Do not modify.
// ---------------------------------------------------------------------------
__global__ __launch_bounds__(256, 1) void gemm_tf32_kernel(float* __restrict__ C) {
    extern __shared__ __align__(1024) unsigned char smem[];
    const uint32_t sb = smem_u32(smem);
    const int tid = threadIdx.x;
    const int wid = tid >> 5;
    const int lane = tid & 31;

    // Grid swizzle: 8-wide n groups (72 % 8 == 0) for L2 reuse.
    const int GN = 8;
    int bid = blockIdx.x;
    int grp = bid / (MTILES * GN);
    int rem = bid % (MTILES * GN);
    int bm = rem / GN;
    int bn = grp * GN + rem % GN;

    const unsigned char* aP = g_ap + (size_t)bm * KCHUNKS * A_TILE_BYTES;
    const unsigned char* wP = g_wp + (size_t)bn * KCHUNKS * W_TILE_BYTES;

    // 8 warps, warp grid 2(m) x 4(n), warp tile 64x64, mma m16n8k8.
    const int tr = lane >> 2;            // 0..7
    const int tc = lane & 3;             // 0..3
    const int wm = wid & 1;              // m warp
    const int wn = wid >> 1;             // n warp 0..3
    const int m_base = wm * 64;
    const int n_base = wn * 64;

    // Relative smem byte addresses (swizzle group XOR reduces to ^tr).
    uint32_t baseA0[4], baseA1[4], baseB[8];
#pragma unroll
    for (int mi = 0; mi < 4; mi++) {
        baseA0[mi] = (uint32_t)(m_base + mi * 16 + tr) * 128 + tc * 4;
        baseA1[mi] = baseA0[mi] + 8 * 128;
    }
#pragma unroll
    for (int ni = 0; ni < 8; ni++)
        baseB[ni] = (uint32_t)A_TILE_BYTES + (uint32_t)(n_base + ni * 8 + tr) * 128 + tc * 4;

    float acc[4][8][4];
#pragma unroll
    for (int mi = 0; mi < 4; mi++)
#pragma unroll
        for (int ni = 0; ni < 8; ni++)
#pragma unroll
            for (int q = 0; q < 4; q++) acc[mi][ni][q] = 0.f;

    auto issue = [&](int c, int s) {
        if (c < KCHUNKS) {
            const unsigned char* srcA = aP + (size_t)c * A_TILE_BYTES;
            const unsigned char* srcW = wP + (size_t)c * W_TILE_BYTES;
            uint32_t dst = sb + SMEM_TILE0 + s * STAGE_BYTES;
#pragma unroll
            for (int i = 0; i < 4; i++) {
                int idx = tid + i * 256;
                cp16(dst + idx * 16, srcA + idx * 16);
            }
#pragma unroll
            for (int i = 0; i < 8; i++) {
                int idx = tid + i * 256;
                cp16(dst + A_TILE_BYTES + idx * 16, srcW + idx * 16);
            }
        }
        asm volatile("cp.async.commit_group;" ::: "memory");
    };

    // Prologue: stages 0..2
    issue(0, 0);
    issue(1, 1);
    issue(2, 2);

#pragma unroll 1
    for (int c = 0; c < KCHUNKS; c++) {
        asm volatile("cp.async.wait_group 2;" ::: "memory");
        __syncthreads();

        const uint32_t st = sb + SMEM_TILE0 + (c & 3) * STAGE_BYTES;
#pragma unroll
        for (int ks = 0; ks < 4; ks++) {
            const uint32_t offe = (uint32_t)((2 * ks) ^ tr) << 4;
            const uint32_t offo = offe ^ 16;
            uint32_t a[4][4];
#pragma unroll
            for (int mi = 0; mi < 4; mi++) {
                a[mi][0] = lds32(st + baseA0[mi] + offe);
                a[mi][1] = lds32(st + baseA1[mi] + offe);
                a[mi][2] = lds32(st + baseA0[mi] + offo);
                a[mi][3] = lds32(st + baseA1[mi] + offo);
            }
            uint32_t b[8][2];
#pragma unroll
            for (int ni = 0; ni < 8; ni++) {
                b[ni][0] = lds32(st + baseB[ni] + offe);
                b[ni][1] = lds32(st + baseB[ni] + offo);
            }
#pragma unroll
            for (int mi = 0; mi < 4; mi++)
#pragma unroll
                for (int ni = 0; ni < 8; ni++)
                    mma_tf32(acc[mi][ni], a[mi], b[ni]);
        }
        __syncthreads();
        issue(c + 3, (c + 3) & 3);
    }

    // Epilogue: c0,c1 at (row, 2tc..), c2,c3 at (row+8, 2tc..)
#pragma unroll
    for (int mi = 0; mi < 4; mi++) {
        size_t r0 = (size_t)bm * BM + m_base + mi * 16 + tr;
        float* p0 = C + r0 * NDIM + (size_t)bn * BN + n_base + 2 * tc;
        float* p1 = p0 + (size_t)8 * NDIM;
#pragma unroll
        for (int ni = 0; ni < 8; ni++) {
            *(float2*)(p0 + ni * 8) = make_float2(acc[mi][ni][0], acc[mi][ni][1]);
            *(float2*)(p1 + ni * 8) = make_float2(acc[mi][ni][2], acc[mi][ni][3]);
        }
    }
}

// ---------------------------------------------------------------------------
extern "C" void kernel_launch(void* const* d_in, const int* in_sizes, int n_in,
                              void* d_out, int out_size) {
    const float* x      = (const float*)d_in[0];
    const float* weight = (const float*)d_in[1];
    const float* scale  = (const float*)d_in[2];
    float* out          = (float*)d_out;

    cudaFuncSetAttribute(gemm_tf32_kernel,
                         cudaFuncAttributeMaxDynamicSharedMemorySize, SMEM_TOTAL);

    size_t a8 = (size_t)MDIM * KDIM / 8;   // 3,670,016  -> 14336 blocks exact
    size_t w8 = (size_t)NDIM * KDIM / 8;   // 16,515,072 -> 64512 blocks exact
    pack_a_kernel<<<(unsigned)((a8 + 255) / 256), 256>>>(x);
    pack_w_kernel<<<(unsigned)((w8 + 255) / 256), 256>>>(weight, scale);
    gemm_tf32_kernel<<<MTILES * NTILES, 256, SMEM_TOTAL>>>(out);
}

// round 14
// speedup vs baseline: 3.5745x; 3.5745x over previous
#include <cuda_runtime.h>
#include <cstdint>

// ---------------------------------------------------------------------------
// C[4096,18432] = A[4096,7168] * W[18432,7168]^T with per-128x128 block scales.
//  Pass 1: pack kernels  -> dequant + cvt.rna.tf32 + SW128 swizzle, tile-major.
//  Pass 2: GEMM          -> tcgen05 (if arch-specific pass exists) else
//                           mma.sync.m16n8k8 tf32 + cp.async 4-stage pipeline.
// ---------------------------------------------------------------------------

#define MDIM 4096
#define NDIM 18432
#define KDIM 7168
#define BM 128
#define BN 256
#define BK 32
#define KCHUNKS (KDIM / BK)          // 224
#define MTILES (MDIM / BM)           // 32
#define NTILES (NDIM / BN)           // 72
#define STAGES 4

#define A_TILE_BYTES (BM * 128)      // 16384 (128 rows x 32 tf32)
#define W_TILE_BYTES (BN * 128)      // 32768 (256 rows x 32 tf32)
#define STAGE_BYTES  (A_TILE_BYTES + W_TILE_BYTES)        // 49152
#define SMEM_TILE0   1024
#define SMEM_TOTAL   (SMEM_TILE0 + STAGES * STAGE_BYTES)  // 197632

__device__ __align__(1024) unsigned char g_ap[(size_t)MDIM * KDIM * 4];
__device__ __align__(1024) unsigned char g_wp[(size_t)NDIM * KDIM * 4];

// ---------------------------------------------------------------------------
__device__ __forceinline__ uint32_t smem_u32(const void* p) {
    uint32_t a;
    asm("{ .reg .u64 t; cvta.to.shared.u64 t, %1; cvt.u32.u64 %0, t; }" : "=r"(a) : "l"(p));
    return a;
}
__device__ __forceinline__ float rna_tf32(float x) {
    uint32_t u;
    asm("cvt.rna.tf32.f32 %0, %1;" : "=r"(u) : "f"(x));
    return __uint_as_float(u);
}
__device__ __forceinline__ uint32_t lds32(uint32_t a) {
    uint32_t v;
    asm volatile("ld.shared.b32 %0, [%1];" : "=r"(v) : "r"(a));
    return v;
}
__device__ __forceinline__ void cp16(uint32_t dst, const void* src) {
    asm volatile("cp.async.cg.shared.global [%0], [%1], 16;"
                 :: "r"(dst), "l"(__cvta_generic_to_global(src)) : "memory");
}
__device__ __forceinline__ void mma_tf32(float* d, const uint32_t* a, const uint32_t* b) {
    asm volatile(
        "mma.sync.aligned.m16n8k8.row.col.f32.tf32.tf32.f32 "
        "{%0,%1,%2,%3}, {%4,%5,%6,%7}, {%8,%9}, {%0,%1,%2,%3};"
        : "+f"(d[0]), "+f"(d[1]), "+f"(d[2]), "+f"(d[3])
        : "r"(a[0]), "r"(a[1]), "r"(a[2]), "r"(a[3]), "r"(b[0]), "r"(b[1]));
}

// ---------------------------------------------------------------------------
// Pack kernels (arch-agnostic). Layout: tile-major; tile = 128B rows (32 tf32),
// SW128 swizzle baked in: byte = row*128 + k*4, sw = byte ^ ((byte>>3)&0x70).
// ---------------------------------------------------------------------------
__global__ __launch_bounds__(256) void pack_a_kernel(const float* __restrict__ x) {
    size_t i = (size_t)blockIdx.x * 256 + threadIdx.x;
    if (i >= (size_t)MDIM * KDIM / 4) return;
    size_t f = i * 4;
    int m = (int)(f / KDIM);
    int k = (int)(f % KDIM);
    float4 v = *(const float4*)(x + f);
    uint32_t off = ((uint32_t)(m & 127) << 7) + ((uint32_t)(k & 31) << 2);
    uint32_t sw = off ^ ((off >> 3) & 0x70);
    unsigned char* dst = g_ap + ((size_t)(m >> 7) * KCHUNKS + (k >> 5)) * A_TILE_BYTES + sw;
    *(float4*)dst = make_float4(rna_tf32(v.x), rna_tf32(v.y), rna_tf32(v.z), rna_tf32(v.w));
}

__global__ __launch_bounds__(256) void pack_w_kernel(const float* __restrict__ w,
                                                     const float* __restrict__ scale) {
    size_t i = (size_t)blockIdx.x * 256 + threadIdx.x;
    if (i >= (size_t)NDIM * KDIM / 4) return;
    size_t f = i * 4;
    int n = (int)(f / KDIM);
    int k = (int)(f % KDIM);
    float4 v = *(const float4*)(w + f);
    float s = scale[(size_t)(n >> 7) * (KDIM / 128) + (k >> 7)];
    uint32_t off = ((uint32_t)(n & 255) << 7) + ((uint32_t)(k & 31) << 2);
    uint32_t sw = off ^ ((off >> 3) & 0x70);
    unsigned char* dst = g_wp + ((size_t)(n >> 8) * KCHUNKS + (k >> 5)) * W_TILE_BYTES + sw;
    *(float4*)dst = make_float4(rna_tf32(v.x * s), rna_tf32(v.y * s),
                                rna_tf32(v.z * s), rna_tf32(v.w * s));
}

// ---------------------------------------------------------------------------
#if defined(__CUDA_ARCH_FEAT_SM103_ALL) || defined(__CUDA_ARCH_FEAT_SM100_ALL)
#define HAVE_TCGEN05 1
#else
#define HAVE_TCGEN05 0
#endif

#if HAVE_TCGEN05
__device__ __forceinline__ uint32_t elect_one_pred() {
    uint32_t p;
    asm volatile("{ .reg .pred p; elect.sync _|p, 0xFFFFFFFF; selp.b32 %0, 1, 0, p; }" : "=r"(p));
    return p;
}
#define MBARRIER_INIT(addr, cnt) \
    asm volatile("mbarrier.init.shared.b64 [%0], %1;" :: "r"((uint32_t)(addr)), "r"((uint32_t)(cnt)) : "memory")
#define MBARRIER_EXPECT_TX(addr, bytes) \
    asm volatile("mbarrier.arrive.expect_tx.shared.b64 _, [%0], %1;" :: "r"((uint32_t)(addr)), "r"((uint32_t)(bytes)) : "memory")
#define MBARRIER_WAIT_PARITY(addr, par) do {                                    \
    uint32_t _m = (uint32_t)(addr), _p = (uint32_t)(par), _d;                   \
    asm volatile("{ .reg .pred p; mbarrier.try_wait.parity.acquire.cta.shared::cta.b64 p, [%1], %2; selp.b32 %0, 1, 0, p; }" \
                 : "=r"(_d) : "r"(_m), "r"(_p) : "memory");                     \
    if (!_d) {                                                                  \
        asm volatile("{ .reg .pred P1; WL_%=: mbarrier.try_wait.parity.acquire.cta.shared::cta.b64 P1, [%0], %1, 0x989680;" \
                     " @P1 bra.uni WD_%=; bra.uni WL_%=; WD_%=: }"              \
                     :: "r"(_m), "r"(_p) : "memory");                           \
    } } while (0)
#endif

// ---------------------------------------------------------------------------
__global__ __launch_bounds__(256, 1) void gemm_tf32_kernel(float* __restrict__ C) {
    extern __shared__ __align__(1024) unsigned char smem[];
    const uint32_t sb = smem_u32(smem);
    const int tid = threadIdx.x;
    const int wid = tid >> 5;
    const int lane = tid & 31;

    // Grid swizzle: 8-wide n groups (72 % 8 == 0) for L2 reuse.
    const int GN = 8;
    int bid = blockIdx.x;
    int grp = bid / (MTILES * GN);
    int rem = bid % (MTILES * GN);
    int bm = rem / GN;
    int bn = grp * GN + rem % GN;

    const unsigned char* aP = g_ap + (size_t)bm * KCHUNKS * A_TILE_BYTES;
    const unsigned char* wP = g_wp + (size_t)bn * KCHUNKS * W_TILE_BYTES;

#if HAVE_TCGEN05
    // ---------------- tcgen05 tf32 path (only if arch-specific pass exists) --
    const uint32_t mb_full0 = sb + 64, mb_empty0 = sb + 96, mb_done = sb + 128;
    if (tid == 0) {
        for (int s = 0; s < STAGES; s++) {
            MBARRIER_INIT(mb_full0 + 8 * s, 1);
            MBARRIER_INIT(mb_empty0 + 8 * s, 1);
        }
        MBARRIER_INIT(mb_done, 1);
    }
    if (wid == 0)
        asm volatile("tcgen05.alloc.cta_group::1.sync.aligned.shared::cta.b32 [%0], 512;"
                     :: "r"(sb) : "memory");
    __syncthreads();
    uint32_t tmem;
    asm volatile("ld.shared.b32 %0, [%1];" : "=r"(tmem) : "r"(sb));

    const uint32_t IDESC = (1u << 4) | (2u << 7) | (2u << 10) | ((BN / 8) << 17) | ((BM / 16) << 24);
    const uint64_t dbase = (uint64_t(2) << 61) | (uint64_t(1) << 46) |
                           (uint64_t(64) << 32) | (uint64_t(1) << 16);

    if (wid == 0) {
        if (elect_one_pred()) {
            int s = 0, ph = 1;
            for (int c = 0; c < KCHUNKS; c++) {
                MBARRIER_WAIT_PARITY(mb_empty0 + 8 * s, ph);
                MBARRIER_EXPECT_TX(mb_full0 + 8 * s, STAGE_BYTES);
                uint32_t tile = sb + SMEM_TILE0 + s * STAGE_BYTES;
                asm volatile("cp.async.bulk.shared::cta.global.mbarrier::complete_tx::bytes [%0], [%1], %2, [%3];"
                    :: "r"(tile), "l"(__cvta_generic_to_global(aP + (size_t)c * A_TILE_BYTES)),
                       "r"((uint32_t)A_TILE_BYTES), "r"(mb_full0 + 8 * s) : "memory");
                asm volatile("cp.async.bulk.shared::cta.global.mbarrier::complete_tx::bytes [%0], [%1], %2, [%3];"
                    :: "r"(tile + A_TILE_BYTES), "l"(__cvta_generic_to_global(wP + (size_t)c * W_TILE_BYTES)),
                       "r"((uint32_t)W_TILE_BYTES), "r"(mb_full0 + 8 * s) : "memory");
                if (++s == STAGES) { s = 0; ph ^= 1; }
            }
        }
    } else if (wid == 1) {
        if (elect_one_pred()) {
            int s = 0, ph = 0;
            for (int c = 0; c < KCHUNKS; c++) {
                MBARRIER_WAIT_PARITY(mb_full0 + 8 * s, ph);
                uint32_t tile = sb + SMEM_TILE0 + s * STAGE_BYTES;
                uint64_t ad = dbase | ((uint64_t)(tile >> 4) & 0x3FFF);
                uint64_t bd = dbase | ((uint64_t)((tile + A_TILE_BYTES) >> 4) & 0x3FFF);
#pragma unroll
                for (int j = 0; j < 4; j++) {
                    uint32_t en = (c > 0 || j > 0) ? 1u : 0u;
                    asm volatile(
                        "{ .reg .pred p; setp.ne.u32 p, %4, 0;"
                        " tcgen05.mma.cta_group::1.kind::tf32 [%0], %1, %2, %3, {%5,%5,%5,%5}, p; }"
                        :: "r"(tmem), "l"(ad + 2 * j), "l"(bd + 2 * j), "r"(IDESC), "r"(en), "r"(0u)
                        : "memory");
                }
                asm volatile("tcgen05.commit.cta_group::1.mbarrier::arrive::one.shared::cluster.b64 [%0];"
                             :: "r"(mb_empty0 + 8 * s) : "memory");
                if (++s == STAGES) { s = 0; ph ^= 1; }
            }
            asm volatile("tcgen05.commit.cta_group::1.mbarrier::arrive::one.shared::cluster.b64 [%0];"
                         :: "r"(mb_done) : "memory");
        }
    }

    MBARRIER_WAIT_PARITY(mb_done, 0);
    asm volatile("tcgen05.fence::after_thread_sync;" ::: "memory");

    {   // 8 warps: subpartition = wid&3, column half = wid>>2 (128 cols each)
        size_t row = (size_t)bm * BM + (wid & 3) * 32 + lane;
        int ncol0 = (wid >> 2) * 128;
        float* cp = C + row * NDIM + (size_t)bn * BN + ncol0;
        uint32_t r[32];
#pragma unroll 1
        for (int cb = 0; cb < 4; cb++) {
            asm volatile("tcgen05.ld.sync.aligned.32x32b.x32.b32 "
                "{%0,%1,%2,%3,%4,%5,%6,%7,%8,%9,%10,%11,%12,%13,%14,%15,"
                "%16,%17,%18,%19,%20,%21,%22,%23,%24,%25,%26,%27,%28,%29,%30,%31}, [%32];"
                : "=r"(r[0]),"=r"(r[1]),"=r"(r[2]),"=r"(r[3]),"=r"(r[4]),"=r"(r[5]),"=r"(r[6]),"=r"(r[7]),
                  "=r"(r[8]),"=r"(r[9]),"=r"(r[10]),"=r"(r[11]),"=r"(r[12]),"=r"(r[13]),"=r"(r[14]),"=r"(r[15]),
                  "=r"(r[16]),"=r"(r[17]),"=r"(r[18]),"=r"(r[19]),"=r"(r[20]),"=r"(r[21]),"=r"(r[22]),"=r"(r[23]),
                  "=r"(r[24]),"=r"(r[25]),"=r"(r[26]),"=r"(r[27]),"=r"(r[28]),"=r"(r[29]),"=r"(r[30]),"=r"(r[31])
                : "r"(tmem + ncol0 + cb * 32));
            asm volatile("tcgen05.wait::ld.sync.aligned;" ::: "memory");
#pragma unroll
            for (int q = 0; q < 8; q++)
                *(float4*)(cp + cb * 32 + q * 4) =
                    make_float4(__uint_as_float(r[4 * q]), __uint_as_float(r[4 * q + 1]),
                                __uint_as_float(r[4 * q + 2]), __uint_as_float(r[4 * q + 3]));
        }
    }
    asm volatile("tcgen05.fence::before_thread_sync;" ::: "memory");
    __syncthreads();
    if (wid == 0) {
        asm volatile("tcgen05.relinquish_alloc_permit.cta_group::1.sync.aligned;");
        asm volatile("tcgen05.dealloc.cta_group::1.sync.aligned.b32 %0, 512;" :: "r"(tmem));
    }

#else
    // ---------------- mma.sync tf32 fallback (base sm_103 target) -----------
    // 8 warps, warp grid 2(m) x 4(n), warp tile 64x64, mma m16n8k8.
    const int tr = lane >> 2;            // 0..7
    const int tc = lane & 3;             // 0..3
    const int wm = wid & 1;              // m warp
    const int wn = wid >> 1;             // n warp 0..3
    const int m_base = wm * 64;
    const int n_base = wn * 64;

    // Relative smem byte addresses (swizzle group XOR reduces to ^tr).
    uint32_t baseA0[4], baseA1[4], baseB[8];
#pragma unroll
    for (int mi = 0; mi < 4; mi++) {
        baseA0[mi] = (uint32_t)(m_base + mi * 16 + tr) * 128 + tc * 4;
        baseA1[mi] = baseA0[mi] + 8 * 128;
    }
#pragma unroll
    for (int ni = 0; ni < 8; ni++)
        baseB[ni] = (uint32_t)A_TILE_BYTES + (uint32_t)(n_base + ni * 8 + tr) * 128 + tc * 4;

    float acc[4][8][4];
#pragma unroll
    for (int mi = 0; mi < 4; mi++)
#pragma unroll
        for (int ni = 0; ni < 8; ni++)
#pragma unroll
            for (int q = 0; q < 4; q++) acc[mi][ni][q] = 0.f;

    auto issue = [&](int c, int s) {
        if (c < KCHUNKS) {
            const unsigned char* srcA = aP + (size_t)c * A_TILE_BYTES;
            const unsigned char* srcW = wP + (size_t)c * W_TILE_BYTES;
            uint32_t dst = sb + SMEM_TILE0 + s * STAGE_BYTES;
#pragma unroll
            for (int i = 0; i < 4; i++) {
                int idx = tid + i * 256;
                cp16(dst + idx * 16, srcA + idx * 16);
            }
#pragma unroll
            for (int i = 0; i < 8; i++) {
                int idx = tid + i * 256;
                cp16(dst + A_TILE_BYTES + idx * 16, srcW + idx * 16);
            }
        }
        asm volatile("cp.async.commit_group;" ::: "memory");
    };

    // Prologue: stages 0..2
    issue(0, 0);
    issue(1, 1);
    issue(2, 2);

#pragma unroll 1
    for (int c = 0; c < KCHUNKS; c++) {
        asm volatile("cp.async.wait_group 2;" ::: "memory");
        __syncthreads();

        const uint32_t st = sb + SMEM_TILE0 + (c & 3) * STAGE_BYTES;
#pragma unroll
        for (int ks = 0; ks < 4; ks++) {
            const uint32_t offe = (uint32_t)((2 * ks) ^ tr) << 4;
            const uint32_t offo = offe ^ 16;
            uint32_t a[4][4];
#pragma unroll
            for (int mi = 0; mi < 4; mi++) {
                a[mi][0] = lds32(st + baseA0[mi] + offe);
                a[mi][1] = lds32(st + baseA1[mi] + offe);
                a[mi][2] = lds32(st + baseA0[mi] + offo);
                a[mi][3] = lds32(st + baseA1[mi] + offo);
            }
            uint32_t b[8][2];
#pragma unroll
            for (int ni = 0; ni < 8; ni++) {
                b[ni][0] = lds32(st + baseB[ni] + offe);
                b[ni][1] = lds32(st + baseB[ni] + offo);
            }
#pragma unroll
            for (int mi = 0; mi < 4; mi++)
#pragma unroll
                for (int ni = 0; ni < 8; ni++)
                    mma_tf32(acc[mi][ni], a[mi], b[ni]);
        }
        __syncthreads();
        issue(c + 3, (c + 3) & 3);
    }

    // Epilogue: c0,c1 at (row, 2tc..), c2,c3 at (row+8, 2tc..)
#pragma unroll
    for (int mi = 0; mi < 4; mi++) {
        size_t r0 = (size_t)bm * BM + m_base + mi * 16 + tr;
        float* p0 = C + r0 * NDIM + (size_t)bn * BN + n_base + 2 * tc;
        float* p1 = p0 + (size_t)8 * NDIM;
#pragma unroll
        for (int ni = 0; ni < 8; ni++) {
            *(float2*)(p0 + ni * 8) = make_float2(acc[mi][ni][0], acc[mi][ni][1]);
            *(float2*)(p1 + ni * 8) = make_float2(acc[mi][ni][2], acc[mi][ni][3]);
        }
    }
#endif
}

// ---------------------------------------------------------------------------
extern "C" void kernel_launch(void* const* d_in, const int* in_sizes, int n_in,
                              void* d_out, int out_size) {
    const float* x      = (const float*)d_in[0];
    const float* weight = (const float*)d_in[1];
    const float* scale  = (const float*)d_in[2];
    float* out          = (float*)d_out;

    cudaFuncSetAttribute(gemm_tf32_kernel,
                         cudaFuncAttributeMaxDynamicSharedMemorySize, SMEM_TOTAL);

    size_t a4 = (size_t)MDIM * KDIM / 4;
    size_t w4 = (size_t)NDIM * KDIM / 4;
    pack_a_kernel<<<(unsigned)((a4 + 255) / 256), 256>>>(x);
    pack_w_kernel<<<(unsigned)((w4 + 255) / 256), 256>>>(weight, scale);
    gemm_tf32_kernel<<<MTILES * NTILES, 256, SMEM_TOTAL>>>(out);
}